// round 1
// baseline (speedup 1.0000x reference)
#include <cuda_runtime.h>
#include <math.h>

// Problem shapes (fixed by the dataset)
#define NB 16384   // batch rows
#define NS 2048    // samples / nystrom dim
#define ND 512     // feature dim

// ---------------------------------------------------------------------------
// Scratch (allocation-free contract: __device__ globals)
// ---------------------------------------------------------------------------
__device__ __align__(16) float g_tmp1[NB * ND];                 // 32 MB
__device__ __align__(16) float g_tmp2[NB * ND];                 // 32 MB  (x_dml)
__device__ __align__(16) float g_sam [NS * ND];                 // 4 MB   (sam_new)
__device__ __align__(16) float g_K   [(long long)NB * NS];      // 128 MB
__device__ __align__(16) float g_H   [(long long)NB * NS];      // 128 MB
__device__ __align__(16) float g_nx  [NB];
__device__ __align__(16) float g_ns  [NS];

// ---------------------------------------------------------------------------
// Activation
// ---------------------------------------------------------------------------
__device__ __forceinline__ float mish_f(float z) {
    // softplus with overflow guard; expf underflow for very negative z is fine
    float sp = (z > 20.0f) ? z : log1pf(expf(z));
    return z * tanhf(sp);
}

enum { EPI_NONE = 0, EPI_BIAS = 1, EPI_BIAS_MISH = 2, EPI_MISH = 3, EPI_RBF = 4 };

// ---------------------------------------------------------------------------
// NT GEMM: C[M,N] = A[M,K] (row-major) * B[N,K]^T (row-major), fused epilogue.
// 128x128 block tile, BK=16, 256 threads, 8x8 register tile per thread.
// All of M,N divisible by 128; K divisible by 16 (true for all call sites).
// ---------------------------------------------------------------------------
template <int EPI>
__global__ void __launch_bounds__(256)
gemm_nt(const float* __restrict__ A, const float* __restrict__ Bm,
        float* __restrict__ C, int M, int N, int K,
        const float* __restrict__ e1,   // bias[N] | nx[M] (RBF)
        const float* __restrict__ e2)   // ns[N] (RBF)
{
    constexpr int BM = 128, BN = 128, BK = 16, PAD = 4;
    __shared__ float As[BK][BM + PAD];
    __shared__ float Bs[BK][BN + PAD];

    const int tid  = threadIdx.x;
    const int tx   = tid & 15;    // 0..15  -> column group
    const int ty   = tid >> 4;    // 0..15  -> row group
    const int lrow = tid >> 2;    // 0..63  loader row
    const int lcol = (tid & 3) << 2; // {0,4,8,12} loader k-offset

    const float* Ab = A  + (size_t)(blockIdx.y * BM) * K;
    const float* Bb = Bm + (size_t)(blockIdx.x * BN) * K;

    float acc[8][8];
#pragma unroll
    for (int i = 0; i < 8; i++)
#pragma unroll
        for (int j = 0; j < 8; j++) acc[i][j] = 0.0f;

    for (int k0 = 0; k0 < K; k0 += BK) {
        // global loads into registers (coalesced float4 along k)
        float4 a0 = *(const float4*)(Ab + (size_t)lrow        * K + k0 + lcol);
        float4 a1 = *(const float4*)(Ab + (size_t)(lrow + 64) * K + k0 + lcol);
        float4 b0 = *(const float4*)(Bb + (size_t)lrow        * K + k0 + lcol);
        float4 b1 = *(const float4*)(Bb + (size_t)(lrow + 64) * K + k0 + lcol);

        __syncthreads();   // previous tile fully consumed before overwrite

        // store transposed: As[k][m], Bs[k][n]
        As[lcol + 0][lrow]      = a0.x; As[lcol + 1][lrow]      = a0.y;
        As[lcol + 2][lrow]      = a0.z; As[lcol + 3][lrow]      = a0.w;
        As[lcol + 0][lrow + 64] = a1.x; As[lcol + 1][lrow + 64] = a1.y;
        As[lcol + 2][lrow + 64] = a1.z; As[lcol + 3][lrow + 64] = a1.w;
        Bs[lcol + 0][lrow]      = b0.x; Bs[lcol + 1][lrow]      = b0.y;
        Bs[lcol + 2][lrow]      = b0.z; Bs[lcol + 3][lrow]      = b0.w;
        Bs[lcol + 0][lrow + 64] = b1.x; Bs[lcol + 1][lrow + 64] = b1.y;
        Bs[lcol + 2][lrow + 64] = b1.z; Bs[lcol + 3][lrow + 64] = b1.w;

        __syncthreads();

#pragma unroll
        for (int kk = 0; kk < BK; kk++) {
            float4 av0 = *(const float4*)&As[kk][ty * 8];
            float4 av1 = *(const float4*)&As[kk][ty * 8 + 4];
            float4 bv0 = *(const float4*)&Bs[kk][tx * 8];
            float4 bv1 = *(const float4*)&Bs[kk][tx * 8 + 4];
            float a[8] = {av0.x, av0.y, av0.z, av0.w, av1.x, av1.y, av1.z, av1.w};
            float b[8] = {bv0.x, bv0.y, bv0.z, bv0.w, bv1.x, bv1.y, bv1.z, bv1.w};
#pragma unroll
            for (int i = 0; i < 8; i++)
#pragma unroll
                for (int j = 0; j < 8; j++)
                    acc[i][j] = fmaf(a[i], b[j], acc[i][j]);
        }
    }

    // ----- fused epilogue, float4 stores -----
    const int row0 = blockIdx.y * BM + ty * 8;
    const int col0 = blockIdx.x * BN + tx * 8;
#pragma unroll
    for (int i = 0; i < 8; i++) {
        const int r = row0 + i;
        float nr = 0.0f;
        if (EPI == EPI_RBF) nr = e1[r];
        float vals[8];
#pragma unroll
        for (int j = 0; j < 8; j++) {
            float v = acc[i][j];
            const int c = col0 + j;
            if (EPI == EPI_BIAS)           v = v + e1[c];
            else if (EPI == EPI_BIAS_MISH) v = mish_f(v + e1[c]);
            else if (EPI == EPI_MISH)      v = mish_f(v);
            else if (EPI == EPI_RBF) {
                float d2 = nr + e2[c] - 2.0f * v;
                v = expf(-sqrtf(fmaxf(d2, 0.0f)));
            }
            vals[j] = v;
        }
        float4* cp = (float4*)(C + (size_t)r * N + col0);
        cp[0] = make_float4(vals[0], vals[1], vals[2], vals[3]);
        cp[1] = make_float4(vals[4], vals[5], vals[6], vals[7]);
    }
}

// ---------------------------------------------------------------------------
// Row squared-norms: one 128-thread block per row, ND=512 -> one float4/thread
// ---------------------------------------------------------------------------
__global__ void __launch_bounds__(128)
rownorm2(const float* __restrict__ X, float* __restrict__ out)
{
    const int row = blockIdx.x;
    const float4 v = *((const float4*)(X + (size_t)row * ND) + threadIdx.x);
    float s = v.x * v.x + v.y * v.y + v.z * v.z + v.w * v.w;
#pragma unroll
    for (int o = 16; o; o >>= 1) s += __shfl_down_sync(0xffffffffu, s, o);
    __shared__ float ws[4];
    const int lane = threadIdx.x & 31, w = threadIdx.x >> 5;
    if (lane == 0) ws[w] = s;
    __syncthreads();
    if (threadIdx.x == 0) out[row] = ws[0] + ws[1] + ws[2] + ws[3];
}

// ---------------------------------------------------------------------------
// Launch
// ---------------------------------------------------------------------------
extern "C" void kernel_launch(void* const* d_in, const int* in_sizes, int n_in,
                              void* d_out, int out_size)
{
    const float* x   = (const float*)d_in[0];
    const float* sm  = (const float*)d_in[1];
    const float* W1  = (const float*)d_in[2];
    const float* b1  = (const float*)d_in[3];
    const float* W2  = (const float*)d_in[4];
    const float* b2  = (const float*)d_in[5];
    const float* Wn1 = (const float*)d_in[6];
    const float* Wn2 = (const float*)d_in[7];
    float* out = (float*)d_out;

    float *tmp1, *tmp2, *sam, *Kb, *Hb, *nx, *ns;
    cudaGetSymbolAddress((void**)&tmp1, g_tmp1);
    cudaGetSymbolAddress((void**)&tmp2, g_tmp2);
    cudaGetSymbolAddress((void**)&sam,  g_sam);
    cudaGetSymbolAddress((void**)&Kb,   g_K);
    cudaGetSymbolAddress((void**)&Hb,   g_H);
    cudaGetSymbolAddress((void**)&nx,   g_nx);
    cudaGetSymbolAddress((void**)&ns,   g_ns);

    const dim3 blk(256);

    // ---- dml(samples): sam_new = mish(samples@W1^T+b1)@W2^T + b2
    gemm_nt<EPI_BIAS_MISH><<<dim3(ND / 128, NS / 128), blk>>>(sm,   W1, tmp1, NS, ND, ND, b1, nullptr);
    gemm_nt<EPI_BIAS>     <<<dim3(ND / 128, NS / 128), blk>>>(tmp1, W2, sam,  NS, ND, ND, b2, nullptr);
    rownorm2<<<NS, 128>>>(sam, ns);

    // ---- dml(x): x_dml
    gemm_nt<EPI_BIAS_MISH><<<dim3(ND / 128, NB / 128), blk>>>(x,    W1, tmp1, NB, ND, ND, b1, nullptr);
    gemm_nt<EPI_BIAS>     <<<dim3(ND / 128, NB / 128), blk>>>(tmp1, W2, tmp2, NB, ND, ND, b2, nullptr);
    rownorm2<<<NB, 128>>>(tmp2, nx);

    // ---- K = exp(-sqrt(max(nx + ns - 2*x_dml@sam_new^T, 0)))
    gemm_nt<EPI_RBF><<<dim3(NS / 128, NB / 128), blk>>>(tmp2, sam, Kb, NB, NS, ND, nx, ns);

    // ---- h = mish(K @ Wn1^T)
    gemm_nt<EPI_MISH><<<dim3(NS / 128, NB / 128), blk>>>(Kb, Wn1, Hb, NB, NS, NS, nullptr, nullptr);

    // ---- out = h @ Wn2^T
    gemm_nt<EPI_NONE><<<dim3(NS / 128, NB / 128), blk>>>(Hb, Wn2, out, NB, NS, NS, nullptr, nullptr);
}

// round 3
// speedup vs baseline: 2.7811x; 2.7811x over previous
#include <cuda_runtime.h>
#include <cstdint>
#include <math.h>

#define NB 16384
#define NS 2048
#define ND 512

// ---------------------------------------------------------------------------
// Scratch (__device__ globals — allocation-free contract)
// ---------------------------------------------------------------------------
__device__ __align__(16) float g_tmp1 [NB * ND];             // dml hidden (rounded)
__device__ __align__(16) float g_tmp2h[NB * ND];             // x_dml hi
__device__ __align__(16) float g_tmp2l[NB * ND];             // x_dml lo
__device__ __align__(16) float g_samh [NS * ND];             // sam_new hi
__device__ __align__(16) float g_saml [NS * ND];             // sam_new lo
__device__ __align__(16) float g_K    [(long long)NB * NS];  // K (rounded)
__device__ __align__(16) float g_H    [(long long)NB * NS];  // mish(K@Wn1) (rounded)
__device__ __align__(16) float g_nx   [NB];
__device__ __align__(16) float g_ns   [NS];
__device__ __align__(16) float g_rx   [NB * ND];
__device__ __align__(16) float g_rsm  [NS * ND];
__device__ __align__(16) float g_rW1  [ND * ND];
__device__ __align__(16) float g_rW2  [ND * ND];
__device__ __align__(16) float g_rWn1 [NS * NS];
__device__ __align__(16) float g_rWn2 [NS * NS];

// ---------------------------------------------------------------------------
// Helpers
// ---------------------------------------------------------------------------
__device__ __forceinline__ uint32_t smem_u32(const void* p) {
    uint32_t a;
    asm("{ .reg .u64 t; cvta.to.shared.u64 t, %1; cvt.u32.u64 %0, t; }" : "=r"(a) : "l"(p));
    return a;
}
__device__ __forceinline__ float tf32_rna(float x) {
    uint32_t r;
    asm("cvt.rna.tf32.f32 %0, %1;" : "=r"(r) : "f"(x));
    return __uint_as_float(r);
}
__device__ __forceinline__ float mish_f(float z) {
    float sp = (z > 20.0f) ? z : log1pf(expf(z));
    return z * tanhf(sp);
}
__device__ __forceinline__ void cp_async16(uint32_t saddr, const void* gaddr) {
    asm volatile("cp.async.cg.shared.global [%0], [%1], 16;" :: "r"(saddr), "l"(gaddr) : "memory");
}
__device__ __forceinline__ void cp_commit() {
    asm volatile("cp.async.commit_group;" ::: "memory");
}
__device__ __forceinline__ void ldsm4(uint32_t* d, uint32_t addr) {
    asm volatile("ldmatrix.sync.aligned.m8n8.x4.shared.b16 {%0,%1,%2,%3}, [%4];"
                 : "=r"(d[0]), "=r"(d[1]), "=r"(d[2]), "=r"(d[3]) : "r"(addr));
}
__device__ __forceinline__ void mma_tf32(float* c, const uint32_t* a, uint32_t b0, uint32_t b1) {
    asm volatile("mma.sync.aligned.m16n8k8.row.col.f32.tf32.tf32.f32 "
                 "{%0,%1,%2,%3}, {%4,%5,%6,%7}, {%8,%9}, {%0,%1,%2,%3};"
                 : "+f"(c[0]), "+f"(c[1]), "+f"(c[2]), "+f"(c[3])
                 : "r"(a[0]), "r"(a[1]), "r"(a[2]), "r"(a[3]), "r"(b0), "r"(b1));
}

enum { EPI_NONE = 0, EPI_BIAS = 1, EPI_BIAS_MISH = 2, EPI_MISH = 3, EPI_RBF = 4 };
enum { ST_RAW = 0, ST_ROUND = 1, ST_SPLIT = 2 };

// ---------------------------------------------------------------------------
// tf32 mma.sync GEMM:  C[M,N] = A[M,K] * B[N,K]^T (both row-major, K-major)
// CTA 128x256, 8 warps (2m x 4n) of 64x64 warp tiles. BK=32 floats, 3 stages
// of cp.async. SPLIT_IN: 3-phase split-tf32 (Ah*Bh + Al*Bh + Ah*Bl).
// ---------------------------------------------------------------------------
#define STAGE_FL 12288           // (128 + 256) * 32 floats
#define STAGE_BY 49152
#define A_BY 16384               // A part of a stage in bytes
#define DSMEM_BY (3 * STAGE_BY)

template <int EPI, int STOREMODE, bool SPLIT_IN>
__global__ void __launch_bounds__(256, 1)
gemm_mma(const float* __restrict__ Ah, const float* __restrict__ Al,
         const float* __restrict__ Bh, const float* __restrict__ Bl,
         float* __restrict__ Ch, float* __restrict__ Cl,
         int M, int N, int K,
         const float* __restrict__ e1, const float* __restrict__ e2)
{
    extern __shared__ float smem[];
    const uint32_t sbase = smem_u32(smem);

    const int tid  = threadIdx.x;
    const int wid  = tid >> 5;
    const int lane = tid & 31;
    const int wm   = wid & 1;        // 0..1
    const int wn   = wid >> 1;       // 0..3
    const int kper = K >> 5;
    const int nk   = SPLIT_IN ? 3 * kper : kper;

    const uint32_t rowA0 = blockIdx.y * 128;
    const uint32_t rowB0 = blockIdx.x * 256;

    // ---- producer per-thread chunk tables (16B chunks) ----
    uint32_t sAo[4], gAo[4], sBo[8], gBo[8];
#pragma unroll
    for (int i = 0; i < 4; i++) {
        int c = tid + i * 256, row = c >> 3, ch = c & 7;
        sAo[i] = (uint32_t)((row * 8 + (ch ^ (row & 7))) * 16);
        gAo[i] = (rowA0 + row) * (uint32_t)K + ch * 4;
    }
#pragma unroll
    for (int i = 0; i < 8; i++) {
        int c = tid + i * 256, row = c >> 3, ch = c & 7;
        sBo[i] = (uint32_t)((row * 8 + (ch ^ (row & 7))) * 16);
        gBo[i] = (rowB0 + row) * (uint32_t)K + ch * 4;
    }

    auto issue = [&](int fi) {
        const int s  = fi % 3;
        int ph = 0, kk = fi;
        if (SPLIT_IN) { ph = fi / kper; kk = fi - ph * kper; }
        const float* gA = (ph == 1) ? Al : Ah;
        const float* gB = (ph == 2) ? Bl : Bh;
        const uint32_t k0 = (uint32_t)kk * 32;
        const uint32_t sA = sbase + s * STAGE_BY;
        const uint32_t sB = sA + A_BY;
#pragma unroll
        for (int i = 0; i < 4; i++) cp_async16(sA + sAo[i], gA + gAo[i] + k0);
#pragma unroll
        for (int i = 0; i < 8; i++) cp_async16(sB + sBo[i], gB + gBo[i] + k0);
        cp_commit();
    };

    // ---- consumer per-lane fragment address constants ----
    const int r8    = lane & 7;
    const int matId = lane >> 3;
    const int mrow  = ((matId & 1) << 3) + r8;  // row within 16-row tile
    const int mhi   = matId >> 1;               // chunk half
    uint32_t csw[4], aRow[4], bRow[4];
#pragma unroll
    for (int ks = 0; ks < 4; ks++) csw[ks] = (uint32_t)(((2 * ks + mhi) ^ r8) << 4);
#pragma unroll
    for (int t = 0; t < 4; t++) {
        aRow[t] = (uint32_t)((wm * 64 + t * 16 + mrow) * 128);
        bRow[t] = (uint32_t)((wn * 64 + t * 16 + mrow) * 128) + A_BY;
    }

    float acc[4][8][4];
#pragma unroll
    for (int mt = 0; mt < 4; mt++)
#pragma unroll
        for (int nt = 0; nt < 8; nt++)
#pragma unroll
            for (int q = 0; q < 4; q++) acc[mt][nt][q] = 0.0f;

    // ---- pipeline ----
    issue(0);
    issue(1);

#pragma unroll 1
    for (int fi = 0; fi < nk; ++fi) {
        if (fi + 1 < nk) asm volatile("cp.async.wait_group 1;" ::: "memory");
        else             asm volatile("cp.async.wait_group 0;" ::: "memory");
        __syncthreads();
        if (fi + 2 < nk) issue(fi + 2);

        const uint32_t st = sbase + (fi % 3) * STAGE_BY;
#pragma unroll
        for (int ks = 0; ks < 4; ks++) {
            uint32_t a[4][4], bb[4][4];
#pragma unroll
            for (int mt = 0; mt < 4; mt++) ldsm4(a[mt],  st + aRow[mt] + csw[ks]);
#pragma unroll
            for (int np = 0; np < 4; np++) ldsm4(bb[np], st + bRow[np] + csw[ks]);
#pragma unroll
            for (int mt = 0; mt < 4; mt++)
#pragma unroll
                for (int nt = 0; nt < 8; nt++)
                    mma_tf32(acc[mt][nt], a[mt], bb[nt >> 1][nt & 1], bb[nt >> 1][2 + (nt & 1)]);
        }
    }

    // ---- epilogue: direct global stores (float2) ----
    const int gid = lane >> 2, tig = lane & 3;
#pragma unroll
    for (int mt = 0; mt < 4; mt++) {
        const int row = blockIdx.y * 128 + wm * 64 + mt * 16 + gid;
        float nr0 = 0.0f, nr8 = 0.0f;
        if (EPI == EPI_RBF) { nr0 = __ldg(e1 + row); nr8 = __ldg(e1 + row + 8); }
#pragma unroll
        for (int nt = 0; nt < 8; nt++) {
            const int col = blockIdx.x * 256 + wn * 64 + nt * 8 + tig * 2;
            float ec0 = 0.0f, ec1 = 0.0f;
            if (EPI == EPI_BIAS || EPI == EPI_BIAS_MISH || EPI == EPI_RBF) {
                const float* ee = (EPI == EPI_RBF) ? e2 : e1;
                ec0 = __ldg(ee + col); ec1 = __ldg(ee + col + 1);
            }
            float v[4] = {acc[mt][nt][0], acc[mt][nt][1], acc[mt][nt][2], acc[mt][nt][3]};
#pragma unroll
            for (int q = 0; q < 4; q++) {
                const float ec = (q & 1) ? ec1 : ec0;
                const float nr = (q < 2) ? nr0 : nr8;
                if (EPI == EPI_BIAS)           v[q] = v[q] + ec;
                else if (EPI == EPI_BIAS_MISH) v[q] = mish_f(v[q] + ec);
                else if (EPI == EPI_MISH)      v[q] = mish_f(v[q]);
                else if (EPI == EPI_RBF) {
                    float d2 = nr + ec - 2.0f * v[q];
                    v[q] = expf(-sqrtf(fmaxf(d2, 0.0f)));
                }
            }
            if (STOREMODE == ST_SPLIT) {
                float h0 = tf32_rna(v[0]), h1 = tf32_rna(v[1]);
                float h2 = tf32_rna(v[2]), h3 = tf32_rna(v[3]);
                *(float2*)(Ch + (size_t)row * N + col)       = make_float2(h0, h1);
                *(float2*)(Ch + (size_t)(row + 8) * N + col) = make_float2(h2, h3);
                *(float2*)(Cl + (size_t)row * N + col)       =
                    make_float2(tf32_rna(v[0] - h0), tf32_rna(v[1] - h1));
                *(float2*)(Cl + (size_t)(row + 8) * N + col) =
                    make_float2(tf32_rna(v[2] - h2), tf32_rna(v[3] - h3));
            } else {
                if (STOREMODE == ST_ROUND) {
                    v[0] = tf32_rna(v[0]); v[1] = tf32_rna(v[1]);
                    v[2] = tf32_rna(v[2]); v[3] = tf32_rna(v[3]);
                }
                *(float2*)(Ch + (size_t)row * N + col)       = make_float2(v[0], v[1]);
                *(float2*)(Ch + (size_t)(row + 8) * N + col) = make_float2(v[2], v[3]);
            }
        }
    }
}

// ---------------------------------------------------------------------------
// tf32 round copy + split row squared-norms
// ---------------------------------------------------------------------------
__global__ void __launch_bounds__(256)
round_tf32_k(const float4* __restrict__ in, float4* __restrict__ out, int n4)
{
    int i = blockIdx.x * 256 + threadIdx.x;
    if (i < n4) {
        float4 v = in[i];
        v.x = tf32_rna(v.x); v.y = tf32_rna(v.y);
        v.z = tf32_rna(v.z); v.w = tf32_rna(v.w);
        out[i] = v;
    }
}

__global__ void __launch_bounds__(128)
rownorm2_split(const float* __restrict__ Xh, const float* __restrict__ Xl,
               float* __restrict__ out)
{
    const int row = blockIdx.x;
    const float4 h = *((const float4*)(Xh + (size_t)row * ND) + threadIdx.x);
    const float4 l = *((const float4*)(Xl + (size_t)row * ND) + threadIdx.x);
    float a0 = h.x + l.x, a1 = h.y + l.y, a2 = h.z + l.z, a3 = h.w + l.w;
    float s = a0 * a0 + a1 * a1 + a2 * a2 + a3 * a3;
#pragma unroll
    for (int o = 16; o; o >>= 1) s += __shfl_down_sync(0xffffffffu, s, o);
    __shared__ float ws[4];
    const int lane = threadIdx.x & 31, w = threadIdx.x >> 5;
    if (lane == 0) ws[w] = s;
    __syncthreads();
    if (threadIdx.x == 0) out[row] = ws[0] + ws[1] + ws[2] + ws[3];
}

// ---------------------------------------------------------------------------
// Launch
// ---------------------------------------------------------------------------
extern "C" void kernel_launch(void* const* d_in, const int* in_sizes, int n_in,
                              void* d_out, int out_size)
{
    const float* x   = (const float*)d_in[0];
    const float* sm  = (const float*)d_in[1];
    const float* W1  = (const float*)d_in[2];
    const float* b1  = (const float*)d_in[3];
    const float* W2  = (const float*)d_in[4];
    const float* b2  = (const float*)d_in[5];
    const float* Wn1 = (const float*)d_in[6];
    const float* Wn2 = (const float*)d_in[7];
    float* out = (float*)d_out;

    float *tmp1, *t2h, *t2l, *smh, *sml, *Kb, *Hb, *nx, *ns;
    float *rx, *rsm, *rW1, *rW2, *rWn1, *rWn2;
    cudaGetSymbolAddress((void**)&tmp1, g_tmp1);
    cudaGetSymbolAddress((void**)&t2h,  g_tmp2h);
    cudaGetSymbolAddress((void**)&t2l,  g_tmp2l);
    cudaGetSymbolAddress((void**)&smh,  g_samh);
    cudaGetSymbolAddress((void**)&sml,  g_saml);
    cudaGetSymbolAddress((void**)&Kb,   g_K);
    cudaGetSymbolAddress((void**)&Hb,   g_H);
    cudaGetSymbolAddress((void**)&nx,   g_nx);
    cudaGetSymbolAddress((void**)&ns,   g_ns);
    cudaGetSymbolAddress((void**)&rx,   g_rx);
    cudaGetSymbolAddress((void**)&rsm,  g_rsm);
    cudaGetSymbolAddress((void**)&rW1,  g_rW1);
    cudaGetSymbolAddress((void**)&rW2,  g_rW2);
    cudaGetSymbolAddress((void**)&rWn1, g_rWn1);
    cudaGetSymbolAddress((void**)&rWn2, g_rWn2);

    cudaFuncSetAttribute(gemm_mma<EPI_BIAS_MISH, ST_ROUND, false>, cudaFuncAttributeMaxDynamicSharedMemorySize, DSMEM_BY);
    cudaFuncSetAttribute(gemm_mma<EPI_BIAS,      ST_SPLIT, false>, cudaFuncAttributeMaxDynamicSharedMemorySize, DSMEM_BY);
    cudaFuncSetAttribute(gemm_mma<EPI_RBF,       ST_ROUND, true >, cudaFuncAttributeMaxDynamicSharedMemorySize, DSMEM_BY);
    cudaFuncSetAttribute(gemm_mma<EPI_MISH,      ST_ROUND, false>, cudaFuncAttributeMaxDynamicSharedMemorySize, DSMEM_BY);
    cudaFuncSetAttribute(gemm_mma<EPI_NONE,      ST_RAW,   false>, cudaFuncAttributeMaxDynamicSharedMemorySize, DSMEM_BY);

    // round operands to tf32 (rna; HW path truncates, so pre-round unbiased)
    round_tf32_k<<<NB * ND / 4 / 256, 256>>>((const float4*)x,   (float4*)rx,   NB * ND / 4);
    round_tf32_k<<<NS * ND / 4 / 256, 256>>>((const float4*)sm,  (float4*)rsm,  NS * ND / 4);
    round_tf32_k<<<ND * ND / 4 / 256, 256>>>((const float4*)W1,  (float4*)rW1,  ND * ND / 4);
    round_tf32_k<<<ND * ND / 4 / 256, 256>>>((const float4*)W2,  (float4*)rW2,  ND * ND / 4);
    round_tf32_k<<<NS * NS / 4 / 256, 256>>>((const float4*)Wn1, (float4*)rWn1, NS * NS / 4);
    round_tf32_k<<<NS * NS / 4 / 256, 256>>>((const float4*)Wn2, (float4*)rWn2, NS * NS / 4);

    const dim3 blk(256);

    // dml(samples)
    gemm_mma<EPI_BIAS_MISH, ST_ROUND, false><<<dim3(ND / 256, NS / 128), blk, DSMEM_BY>>>(
        rsm, nullptr, rW1, nullptr, tmp1, nullptr, NS, ND, ND, b1, nullptr);
    gemm_mma<EPI_BIAS, ST_SPLIT, false><<<dim3(ND / 256, NS / 128), blk, DSMEM_BY>>>(
        tmp1, nullptr, rW2, nullptr, smh, sml, NS, ND, ND, b2, nullptr);
    rownorm2_split<<<NS, 128>>>(smh, sml, ns);

    // dml(x)
    gemm_mma<EPI_BIAS_MISH, ST_ROUND, false><<<dim3(ND / 256, NB / 128), blk, DSMEM_BY>>>(
        rx, nullptr, rW1, nullptr, tmp1, nullptr, NB, ND, ND, b1, nullptr);
    gemm_mma<EPI_BIAS, ST_SPLIT, false><<<dim3(ND / 256, NB / 128), blk, DSMEM_BY>>>(
        tmp1, nullptr, rW2, nullptr, t2h, t2l, NB, ND, ND, b2, nullptr);
    rownorm2_split<<<NB, 128>>>(t2h, t2l, nx);

    // K = exp(-sqrt(max(nx + ns - 2*x_dml@sam^T, 0)))  — split-tf32 (3 phases)
    gemm_mma<EPI_RBF, ST_ROUND, true><<<dim3(NS / 256, NB / 128), blk, DSMEM_BY>>>(
        t2h, t2l, smh, sml, Kb, nullptr, NB, NS, ND, nx, ns);

    // h = mish(K @ Wn1^T)
    gemm_mma<EPI_MISH, ST_ROUND, false><<<dim3(NS / 256, NB / 128), blk, DSMEM_BY>>>(
        Kb, nullptr, rWn1, nullptr, Hb, nullptr, NB, NS, NS, nullptr, nullptr);

    // out = h @ Wn2^T
    gemm_mma<EPI_NONE, ST_RAW, false><<<dim3(NS / 256, NB / 128), blk, DSMEM_BY>>>(
        Hb, nullptr, rWn2, nullptr, out, nullptr, NB, NS, NS, nullptr, nullptr);
}

// round 4
// speedup vs baseline: 3.3847x; 1.2171x over previous
#include <cuda_runtime.h>
#include <cstdint>
#include <math.h>

#define NB 16384
#define NS 2048
#define ND 512

// ---------------------------------------------------------------------------
// Scratch (__device__ globals — allocation-free contract)
// ---------------------------------------------------------------------------
__device__ __align__(16) float g_tmp1 [NB * ND];             // dml hidden (rounded)
__device__ __align__(16) float g_tmp2h[NB * ND];             // x_dml hi
__device__ __align__(16) float g_tmp2l[NB * ND];             // x_dml lo
__device__ __align__(16) float g_samh [NS * ND];             // sam_new hi
__device__ __align__(16) float g_saml [NS * ND];             // sam_new lo
__device__ __align__(16) float g_K    [(long long)NB * NS];  // K (rounded)
__device__ __align__(16) float g_H    [(long long)NB * NS];  // mish(K@Wn1) (rounded)
__device__ __align__(16) float g_nx   [NB];
__device__ __align__(16) float g_ns   [NS];
__device__ __align__(16) float g_rx   [NB * ND];
__device__ __align__(16) float g_rsm  [NS * ND];
__device__ __align__(16) float g_rW1  [ND * ND];
__device__ __align__(16) float g_rW2  [ND * ND];
__device__ __align__(16) float g_rWn1 [NS * NS];
__device__ __align__(16) float g_rWn2 [NS * NS];

// ---------------------------------------------------------------------------
// Helpers
// ---------------------------------------------------------------------------
__device__ __forceinline__ uint32_t smem_u32(const void* p) {
    uint32_t a;
    asm("{ .reg .u64 t; cvta.to.shared.u64 t, %1; cvt.u32.u64 %0, t; }" : "=r"(a) : "l"(p));
    return a;
}
__device__ __forceinline__ float tf32_rna(float x) {
    uint32_t r;
    asm("cvt.rna.tf32.f32 %0, %1;" : "=r"(r) : "f"(x));
    return __uint_as_float(r);
}
__device__ __forceinline__ float mish_f(float z) {
    float sp = (z > 20.0f) ? z : log1pf(expf(z));
    return z * tanhf(sp);
}
__device__ __forceinline__ void cp_async16(uint32_t saddr, const void* gaddr) {
    asm volatile("cp.async.cg.shared.global [%0], [%1], 16;" :: "r"(saddr), "l"(gaddr) : "memory");
}
__device__ __forceinline__ void cp_commit() {
    asm volatile("cp.async.commit_group;" ::: "memory");
}
__device__ __forceinline__ void ldsm4(uint32_t* d, uint32_t addr) {
    asm volatile("ldmatrix.sync.aligned.m8n8.x4.shared.b16 {%0,%1,%2,%3}, [%4];"
                 : "=r"(d[0]), "=r"(d[1]), "=r"(d[2]), "=r"(d[3]) : "r"(addr));
}
__device__ __forceinline__ void mma_tf32(float* c, const uint32_t* a, uint32_t b0, uint32_t b1) {
    asm volatile("mma.sync.aligned.m16n8k8.row.col.f32.tf32.tf32.f32 "
                 "{%0,%1,%2,%3}, {%4,%5,%6,%7}, {%8,%9}, {%0,%1,%2,%3};"
                 : "+f"(c[0]), "+f"(c[1]), "+f"(c[2]), "+f"(c[3])
                 : "r"(a[0]), "r"(a[1]), "r"(a[2]), "r"(a[3]), "r"(b0), "r"(b1));
}

enum { EPI_NONE = 0, EPI_BIAS = 1, EPI_BIAS_MISH = 2, EPI_MISH = 3, EPI_RBF = 4 };
enum { ST_RAW = 0, ST_ROUND = 1, ST_SPLIT = 2 };

// ---------------------------------------------------------------------------
// tf32 mma.sync GEMM:  C[M,N] = A[M,K] * B[N,K]^T (both row-major, K-major)
// CTA 128x128, 8 warps (2m x 4n) of 64x32 warp tiles. BK=32 floats, 3-stage
// cp.async. 96KB smem -> 2 CTAs/SM. SPLIT_A: 2-pass (Ah@Bh + Al@Bh).
// ---------------------------------------------------------------------------
#define A_BY     16384           // 128 rows * 128B
#define STAGE_BY 32768           // A + B
#define DSMEM_BY (3 * STAGE_BY)  // 98304

template <int EPI, int STOREMODE, bool SPLIT_A>
__global__ void __launch_bounds__(256, 2)
gemm_mma(const float* __restrict__ Ah, const float* __restrict__ Al,
         const float* __restrict__ Bh,
         float* __restrict__ Ch, float* __restrict__ Cl,
         int M, int N, int K,
         const float* __restrict__ e1, const float* __restrict__ e2)
{
    extern __shared__ float smem[];
    const uint32_t sbase = smem_u32(smem);

    const int tid  = threadIdx.x;
    const int wid  = tid >> 5;
    const int lane = tid & 31;
    const int wm   = wid & 1;        // 0..1 (64 rows each)
    const int wn   = wid >> 1;       // 0..3 (32 cols each)
    const int kper = K >> 5;
    const int nk   = SPLIT_A ? 2 * kper : kper;

    const uint32_t rowA0 = blockIdx.y * 128;
    const uint32_t rowB0 = blockIdx.x * 128;

    // ---- producer per-thread chunk tables (16B chunks; 1024 per operand) ----
    uint32_t sOff[4], gAo[4], gBo[4];
#pragma unroll
    for (int i = 0; i < 4; i++) {
        int c = tid + i * 256, row = c >> 3, ch = c & 7;
        sOff[i] = (uint32_t)((row * 8 + (ch ^ (row & 7))) * 16);
        gAo[i]  = (rowA0 + row) * (uint32_t)K + ch * 4;
        gBo[i]  = (rowB0 + row) * (uint32_t)K + ch * 4;
    }

    auto issue = [&](int fi) {
        const int s  = fi % 3;
        int kk = fi;
        const float* gA = Ah;
        if (SPLIT_A && fi >= kper) { gA = Al; kk = fi - kper; }
        const uint32_t k0 = (uint32_t)kk * 32;
        const uint32_t sA = sbase + s * STAGE_BY;
        const uint32_t sB = sA + A_BY;
#pragma unroll
        for (int i = 0; i < 4; i++) cp_async16(sA + sOff[i], gA + gAo[i] + k0);
#pragma unroll
        for (int i = 0; i < 4; i++) cp_async16(sB + sOff[i], Bh + gBo[i] + k0);
        cp_commit();
    };

    // ---- consumer per-lane fragment address constants ----
    const int r8    = lane & 7;
    const int matId = lane >> 3;
    const int mrow  = ((matId & 1) << 3) + r8;
    const int mhi   = matId >> 1;
    uint32_t csw[4], aRow[4], bRow[2];
#pragma unroll
    for (int ks = 0; ks < 4; ks++) csw[ks] = (uint32_t)(((2 * ks + mhi) ^ r8) << 4);
#pragma unroll
    for (int t = 0; t < 4; t++) aRow[t] = (uint32_t)((wm * 64 + t * 16 + mrow) * 128);
#pragma unroll
    for (int t = 0; t < 2; t++) bRow[t] = (uint32_t)((wn * 32 + t * 16 + mrow) * 128) + A_BY;

    float acc[4][4][4];
#pragma unroll
    for (int mt = 0; mt < 4; mt++)
#pragma unroll
        for (int nt = 0; nt < 4; nt++)
#pragma unroll
            for (int q = 0; q < 4; q++) acc[mt][nt][q] = 0.0f;

    // ---- pipeline ----
    issue(0);
    issue(1);

#pragma unroll 1
    for (int fi = 0; fi < nk; ++fi) {
        if (fi + 1 < nk) asm volatile("cp.async.wait_group 1;" ::: "memory");
        else             asm volatile("cp.async.wait_group 0;" ::: "memory");
        __syncthreads();
        if (fi + 2 < nk) issue(fi + 2);

        const uint32_t st = sbase + (fi % 3) * STAGE_BY;
#pragma unroll
        for (int ks = 0; ks < 4; ks++) {
            uint32_t a[4][4], bb[2][4];
#pragma unroll
            for (int mt = 0; mt < 4; mt++) ldsm4(a[mt],  st + aRow[mt] + csw[ks]);
#pragma unroll
            for (int np = 0; np < 2; np++) ldsm4(bb[np], st + bRow[np] + csw[ks]);
#pragma unroll
            for (int mt = 0; mt < 4; mt++)
#pragma unroll
                for (int nt = 0; nt < 4; nt++)
                    mma_tf32(acc[mt][nt], a[mt], bb[nt >> 1][nt & 1], bb[nt >> 1][2 + (nt & 1)]);
        }
    }

    // ---- epilogue: direct global stores (float2) ----
    const int gid = lane >> 2, tig = lane & 3;
#pragma unroll
    for (int mt = 0; mt < 4; mt++) {
        const int row = blockIdx.y * 128 + wm * 64 + mt * 16 + gid;
        float nr0 = 0.0f, nr8 = 0.0f;
        if (EPI == EPI_RBF) { nr0 = __ldg(e1 + row); nr8 = __ldg(e1 + row + 8); }
#pragma unroll
        for (int nt = 0; nt < 4; nt++) {
            const int col = blockIdx.x * 128 + wn * 32 + nt * 8 + tig * 2;
            float ec0 = 0.0f, ec1 = 0.0f;
            if (EPI == EPI_BIAS || EPI == EPI_BIAS_MISH || EPI == EPI_RBF) {
                const float* ee = (EPI == EPI_RBF) ? e2 : e1;
                ec0 = __ldg(ee + col); ec1 = __ldg(ee + col + 1);
            }
            float v[4] = {acc[mt][nt][0], acc[mt][nt][1], acc[mt][nt][2], acc[mt][nt][3]};
#pragma unroll
            for (int q = 0; q < 4; q++) {
                const float ec = (q & 1) ? ec1 : ec0;
                const float nr = (q < 2) ? nr0 : nr8;
                if (EPI == EPI_BIAS)           v[q] = v[q] + ec;
                else if (EPI == EPI_BIAS_MISH) v[q] = mish_f(v[q] + ec);
                else if (EPI == EPI_MISH)      v[q] = mish_f(v[q]);
                else if (EPI == EPI_RBF) {
                    float d2 = nr + ec - 2.0f * v[q];
                    v[q] = expf(-sqrtf(fmaxf(d2, 0.0f)));
                }
            }
            if (STOREMODE == ST_SPLIT) {
                float h0 = tf32_rna(v[0]), h1 = tf32_rna(v[1]);
                float h2 = tf32_rna(v[2]), h3 = tf32_rna(v[3]);
                *(float2*)(Ch + (size_t)row * N + col)       = make_float2(h0, h1);
                *(float2*)(Ch + (size_t)(row + 8) * N + col) = make_float2(h2, h3);
                *(float2*)(Cl + (size_t)row * N + col)       =
                    make_float2(tf32_rna(v[0] - h0), tf32_rna(v[1] - h1));
                *(float2*)(Cl + (size_t)(row + 8) * N + col) =
                    make_float2(tf32_rna(v[2] - h2), tf32_rna(v[3] - h3));
            } else {
                if (STOREMODE == ST_ROUND) {
                    v[0] = tf32_rna(v[0]); v[1] = tf32_rna(v[1]);
                    v[2] = tf32_rna(v[2]); v[3] = tf32_rna(v[3]);
                }
                *(float2*)(Ch + (size_t)row * N + col)       = make_float2(v[0], v[1]);
                *(float2*)(Ch + (size_t)(row + 8) * N + col) = make_float2(v[2], v[3]);
            }
        }
    }
}

// ---------------------------------------------------------------------------
// tf32 round copy + split row squared-norms
// ---------------------------------------------------------------------------
__global__ void __launch_bounds__(256)
round_tf32_k(const float4* __restrict__ in, float4* __restrict__ out, int n4)
{
    int i = blockIdx.x * 256 + threadIdx.x;
    if (i < n4) {
        float4 v = in[i];
        v.x = tf32_rna(v.x); v.y = tf32_rna(v.y);
        v.z = tf32_rna(v.z); v.w = tf32_rna(v.w);
        out[i] = v;
    }
}

__global__ void __launch_bounds__(128)
rownorm2_split(const float* __restrict__ Xh, const float* __restrict__ Xl,
               float* __restrict__ out)
{
    const int row = blockIdx.x;
    const float4 h = *((const float4*)(Xh + (size_t)row * ND) + threadIdx.x);
    const float4 l = *((const float4*)(Xl + (size_t)row * ND) + threadIdx.x);
    float a0 = h.x + l.x, a1 = h.y + l.y, a2 = h.z + l.z, a3 = h.w + l.w;
    float s = a0 * a0 + a1 * a1 + a2 * a2 + a3 * a3;
#pragma unroll
    for (int o = 16; o; o >>= 1) s += __shfl_down_sync(0xffffffffu, s, o);
    __shared__ float ws[4];
    const int lane = threadIdx.x & 31, w = threadIdx.x >> 5;
    if (lane == 0) ws[w] = s;
    __syncthreads();
    if (threadIdx.x == 0) out[row] = ws[0] + ws[1] + ws[2] + ws[3];
}

// ---------------------------------------------------------------------------
// Launch  (ordered so launch #5 — the ncu capture window — is a big GEMM)
// ---------------------------------------------------------------------------
extern "C" void kernel_launch(void* const* d_in, const int* in_sizes, int n_in,
                              void* d_out, int out_size)
{
    const float* x   = (const float*)d_in[0];
    const float* sm  = (const float*)d_in[1];
    const float* W1  = (const float*)d_in[2];
    const float* b1  = (const float*)d_in[3];
    const float* W2  = (const float*)d_in[4];
    const float* b2  = (const float*)d_in[5];
    const float* Wn1 = (const float*)d_in[6];
    const float* Wn2 = (const float*)d_in[7];
    float* out = (float*)d_out;

    float *tmp1, *t2h, *t2l, *smh, *sml, *Kb, *Hb, *nx, *ns;
    float *rx, *rsm, *rW1, *rW2, *rWn1, *rWn2;
    cudaGetSymbolAddress((void**)&tmp1, g_tmp1);
    cudaGetSymbolAddress((void**)&t2h,  g_tmp2h);
    cudaGetSymbolAddress((void**)&t2l,  g_tmp2l);
    cudaGetSymbolAddress((void**)&smh,  g_samh);
    cudaGetSymbolAddress((void**)&sml,  g_saml);
    cudaGetSymbolAddress((void**)&Kb,   g_K);
    cudaGetSymbolAddress((void**)&Hb,   g_H);
    cudaGetSymbolAddress((void**)&nx,   g_nx);
    cudaGetSymbolAddress((void**)&ns,   g_ns);
    cudaGetSymbolAddress((void**)&rx,   g_rx);
    cudaGetSymbolAddress((void**)&rsm,  g_rsm);
    cudaGetSymbolAddress((void**)&rW1,  g_rW1);
    cudaGetSymbolAddress((void**)&rW2,  g_rW2);
    cudaGetSymbolAddress((void**)&rWn1, g_rWn1);
    cudaGetSymbolAddress((void**)&rWn2, g_rWn2);

    cudaFuncSetAttribute(gemm_mma<EPI_BIAS_MISH, ST_ROUND, false>, cudaFuncAttributeMaxDynamicSharedMemorySize, DSMEM_BY);
    cudaFuncSetAttribute(gemm_mma<EPI_BIAS,      ST_SPLIT, false>, cudaFuncAttributeMaxDynamicSharedMemorySize, DSMEM_BY);
    cudaFuncSetAttribute(gemm_mma<EPI_RBF,       ST_ROUND, true >, cudaFuncAttributeMaxDynamicSharedMemorySize, DSMEM_BY);
    cudaFuncSetAttribute(gemm_mma<EPI_MISH,      ST_ROUND, false>, cudaFuncAttributeMaxDynamicSharedMemorySize, DSMEM_BY);
    cudaFuncSetAttribute(gemm_mma<EPI_NONE,      ST_RAW,   false>, cudaFuncAttributeMaxDynamicSharedMemorySize, DSMEM_BY);

    const dim3 blk(256);

    // launches 0..4: rounding kernels
    round_tf32_k<<<NB * ND / 4 / 256, 256>>>((const float4*)x,   (float4*)rx,   NB * ND / 4);
    round_tf32_k<<<ND * ND / 4 / 256, 256>>>((const float4*)W1,  (float4*)rW1,  ND * ND / 4);
    round_tf32_k<<<ND * ND / 4 / 256, 256>>>((const float4*)W2,  (float4*)rW2,  ND * ND / 4);
    round_tf32_k<<<NS * NS / 4 / 256, 256>>>((const float4*)Wn1, (float4*)rWn1, NS * NS / 4);
    round_tf32_k<<<NS * NS / 4 / 256, 256>>>((const float4*)Wn2, (float4*)rWn2, NS * NS / 4);

    // launch 5: dml(x) layer 1 — ncu capture target
    gemm_mma<EPI_BIAS_MISH, ST_ROUND, false><<<dim3(ND / 128, NB / 128), blk, DSMEM_BY>>>(
        rx, nullptr, rW1, tmp1, nullptr, NB, ND, ND, b1, nullptr);
    round_tf32_k<<<NS * ND / 4 / 256, 256>>>((const float4*)sm, (float4*)rsm, NS * ND / 4);
    gemm_mma<EPI_BIAS, ST_SPLIT, false><<<dim3(ND / 128, NB / 128), blk, DSMEM_BY>>>(
        tmp1, nullptr, rW2, t2h, t2l, NB, ND, ND, b2, nullptr);
    rownorm2_split<<<NB, 128>>>(t2h, t2l, nx);

    // dml(samples)
    gemm_mma<EPI_BIAS_MISH, ST_ROUND, false><<<dim3(ND / 128, NS / 128), blk, DSMEM_BY>>>(
        rsm, nullptr, rW1, tmp1, nullptr, NS, ND, ND, b1, nullptr);
    gemm_mma<EPI_BIAS, ST_SPLIT, false><<<dim3(ND / 128, NS / 128), blk, DSMEM_BY>>>(
        tmp1, nullptr, rW2, smh, sml, NS, ND, ND, b2, nullptr);
    rownorm2_split<<<NS, 128>>>(smh, sml, ns);

    // K = exp(-sqrt(max(nx + ns - 2*x_dml@sam^T, 0))) — 2-pass split (x side)
    gemm_mma<EPI_RBF, ST_ROUND, true><<<dim3(NS / 128, NB / 128), blk, DSMEM_BY>>>(
        t2h, t2l, smh, Kb, nullptr, NB, NS, ND, nx, ns);

    // h = mish(K @ Wn1^T)
    gemm_mma<EPI_MISH, ST_ROUND, false><<<dim3(NS / 128, NB / 128), blk, DSMEM_BY>>>(
        Kb, nullptr, rWn1, Hb, nullptr, NB, NS, NS, nullptr, nullptr);

    // out = h @ Wn2^T
    gemm_mma<EPI_NONE, ST_RAW, false><<<dim3(NS / 128, NB / 128), blk, DSMEM_BY>>>(
        Hb, nullptr, rWn2, out, nullptr, NB, NS, NS, nullptr, nullptr);
}

// round 5
// speedup vs baseline: 3.6506x; 1.0785x over previous
#include <cuda_runtime.h>
#include <cstdint>
#include <math.h>

#define NB 16384
#define NS 2048
#define ND 512

// ---------------------------------------------------------------------------
// Scratch (__device__ globals — allocation-free contract)
// ---------------------------------------------------------------------------
__device__ __align__(16) float g_tmp1 [NB * ND];             // dml hidden (rounded)
__device__ __align__(16) float g_xd   [NB * ND];             // x_dml (tf32-rounded)
__device__ __align__(16) float g_sam  [NS * ND];             // sam_new (tf32-rounded)
__device__ __align__(16) float g_K    [(long long)NB * NS];  // K (rounded)
__device__ __align__(16) float g_H    [(long long)NB * NS];  // mish(K@Wn1) (rounded)
__device__ __align__(16) float g_nx   [NB];
__device__ __align__(16) float g_ns   [NS];
__device__ __align__(16) float g_rx   [NB * ND];
__device__ __align__(16) float g_rsm  [NS * ND];
__device__ __align__(16) float g_rW1  [ND * ND];
__device__ __align__(16) float g_rW2  [ND * ND];
__device__ __align__(16) float g_rWn1 [NS * NS];
__device__ __align__(16) float g_rWn2 [NS * NS];

// ---------------------------------------------------------------------------
// Helpers
// ---------------------------------------------------------------------------
__device__ __forceinline__ uint32_t smem_u32(const void* p) {
    uint32_t a;
    asm("{ .reg .u64 t; cvta.to.shared.u64 t, %1; cvt.u32.u64 %0, t; }" : "=r"(a) : "l"(p));
    return a;
}
__device__ __forceinline__ float tf32_rna(float x) {
    uint32_t r;
    asm("cvt.rna.tf32.f32 %0, %1;" : "=r"(r) : "f"(x));
    return __uint_as_float(r);
}
__device__ __forceinline__ float mish_f(float z) {
    float sp = (z > 20.0f) ? z : log1pf(expf(z));
    return z * tanhf(sp);
}
__device__ __forceinline__ void cp_async16(uint32_t saddr, const void* gaddr) {
    asm volatile("cp.async.cg.shared.global [%0], [%1], 16;" :: "r"(saddr), "l"(gaddr) : "memory");
}
__device__ __forceinline__ void cp_commit() {
    asm volatile("cp.async.commit_group;" ::: "memory");
}
__device__ __forceinline__ void ldsm4(uint32_t* d, uint32_t addr) {
    asm volatile("ldmatrix.sync.aligned.m8n8.x4.shared.b16 {%0,%1,%2,%3}, [%4];"
                 : "=r"(d[0]), "=r"(d[1]), "=r"(d[2]), "=r"(d[3]) : "r"(addr));
}
__device__ __forceinline__ void mma_tf32(float* c, const uint32_t* a, uint32_t b0, uint32_t b1) {
    asm volatile("mma.sync.aligned.m16n8k8.row.col.f32.tf32.tf32.f32 "
                 "{%0,%1,%2,%3}, {%4,%5,%6,%7}, {%8,%9}, {%0,%1,%2,%3};"
                 : "+f"(c[0]), "+f"(c[1]), "+f"(c[2]), "+f"(c[3])
                 : "r"(a[0]), "r"(a[1]), "r"(a[2]), "r"(a[3]), "r"(b0), "r"(b1));
}

enum { EPI_NONE = 0, EPI_BIAS = 1, EPI_BIAS_MISH = 2, EPI_MISH = 3, EPI_RBF = 4 };
enum { ST_RAW = 0, ST_ROUND = 1 };

// ---------------------------------------------------------------------------
// tf32 mma.sync GEMM:  C[M,N] = A[M,K] * B[N,K]^T (both row-major, K-major)
// CTA 256x128, 16 warps (8m x 2n) of 32x64 warp tiles. BK=32, 3-stage
// cp.async, 144KB smem, 1 CTA/SM (4 warps/SMSP).
// Intensity = 85 FLOP/B from L2 -> compute-bound (vs 64 @128x128 = L2-bound).
// ---------------------------------------------------------------------------
#define A_BY     32768           // 256 rows * 128B
#define STAGE_BY 49152           // A(32KB) + B(16KB)
#define DSMEM_BY (3 * STAGE_BY)  // 147456

template <int EPI, int STOREMODE>
__global__ void __launch_bounds__(512, 1)
gemm_mma(const float* __restrict__ Ah, const float* __restrict__ Bh,
         float* __restrict__ Ch,
         int M, int N, int K,
         const float* __restrict__ e1, const float* __restrict__ e2)
{
    extern __shared__ float smem[];
    const uint32_t sbase = smem_u32(smem);

    const int tid  = threadIdx.x;
    const int wid  = tid >> 5;
    const int lane = tid & 31;
    const int wm   = wid >> 1;       // 0..7 (32 rows each)
    const int wn   = wid & 1;        // 0..1 (64 cols each)
    const int nk   = K >> 5;

    const uint32_t rowA0 = blockIdx.y * 256;
    const uint32_t rowB0 = blockIdx.x * 128;

    // ---- producer chunk tables: A 2048 chunks, B 1024 chunks (16B each) ----
    uint32_t sAOff[4], gAo[4], sBOff[2], gBo[2];
#pragma unroll
    for (int i = 0; i < 4; i++) {
        int c = tid + i * 512, row = c >> 3, ch = c & 7;
        sAOff[i] = (uint32_t)((row * 8 + (ch ^ (row & 7))) * 16);
        gAo[i]   = (rowA0 + row) * (uint32_t)K + ch * 4;
    }
#pragma unroll
    for (int i = 0; i < 2; i++) {
        int c = tid + i * 512, row = c >> 3, ch = c & 7;
        sBOff[i] = (uint32_t)((row * 8 + (ch ^ (row & 7))) * 16);
        gBo[i]   = (rowB0 + row) * (uint32_t)K + ch * 4;
    }

    auto issue = [&](int fi) {
        const int s = fi % 3;
        const uint32_t k0 = (uint32_t)fi * 32;
        const uint32_t sA = sbase + s * STAGE_BY;
        const uint32_t sB = sA + A_BY;
#pragma unroll
        for (int i = 0; i < 4; i++) cp_async16(sA + sAOff[i], Ah + gAo[i] + k0);
#pragma unroll
        for (int i = 0; i < 2; i++) cp_async16(sB + sBOff[i], Bh + gBo[i] + k0);
        cp_commit();
    };

    // ---- consumer fragment addresses ----
    const int r8    = lane & 7;
    const int matId = lane >> 3;
    const int mrow  = ((matId & 1) << 3) + r8;
    const int mhi   = matId >> 1;
    uint32_t csw[4], aRow[2], bRow[4];
#pragma unroll
    for (int ks = 0; ks < 4; ks++) csw[ks] = (uint32_t)(((2 * ks + mhi) ^ r8) << 4);
#pragma unroll
    for (int t = 0; t < 2; t++) aRow[t] = (uint32_t)((wm * 32 + t * 16 + mrow) * 128);
#pragma unroll
    for (int t = 0; t < 4; t++) bRow[t] = (uint32_t)((wn * 64 + t * 16 + mrow) * 128) + A_BY;

    float acc[2][8][4];
#pragma unroll
    for (int mt = 0; mt < 2; mt++)
#pragma unroll
        for (int nt = 0; nt < 8; nt++)
#pragma unroll
            for (int q = 0; q < 4; q++) acc[mt][nt][q] = 0.0f;

    // ---- 3-stage pipeline ----
    issue(0);
    issue(1);

#pragma unroll 1
    for (int fi = 0; fi < nk; ++fi) {
        if (fi + 1 < nk) asm volatile("cp.async.wait_group 1;" ::: "memory");
        else             asm volatile("cp.async.wait_group 0;" ::: "memory");
        __syncthreads();
        if (fi + 2 < nk) issue(fi + 2);

        const uint32_t st = sbase + (fi % 3) * STAGE_BY;
#pragma unroll
        for (int ks = 0; ks < 4; ks++) {
            uint32_t a[2][4], bb[4][4];
#pragma unroll
            for (int mt = 0; mt < 2; mt++) ldsm4(a[mt],  st + aRow[mt] + csw[ks]);
#pragma unroll
            for (int np = 0; np < 4; np++) ldsm4(bb[np], st + bRow[np] + csw[ks]);
#pragma unroll
            for (int mt = 0; mt < 2; mt++)
#pragma unroll
                for (int nt = 0; nt < 8; nt++)
                    mma_tf32(acc[mt][nt], a[mt], bb[nt >> 1][nt & 1], bb[nt >> 1][2 + (nt & 1)]);
        }
    }

    // ---- epilogue ----
    const int gid = lane >> 2, tig = lane & 3;
#pragma unroll
    for (int mt = 0; mt < 2; mt++) {
        const int row = blockIdx.y * 256 + wm * 32 + mt * 16 + gid;
        float nr0 = 0.0f, nr8 = 0.0f;
        if (EPI == EPI_RBF) { nr0 = __ldg(e1 + row); nr8 = __ldg(e1 + row + 8); }
#pragma unroll
        for (int nt = 0; nt < 8; nt++) {
            const int col = blockIdx.x * 128 + wn * 64 + nt * 8 + tig * 2;
            float ec0 = 0.0f, ec1 = 0.0f;
            if (EPI == EPI_BIAS || EPI == EPI_BIAS_MISH || EPI == EPI_RBF) {
                const float* ee = (EPI == EPI_RBF) ? e2 : e1;
                ec0 = __ldg(ee + col); ec1 = __ldg(ee + col + 1);
            }
            float v[4] = {acc[mt][nt][0], acc[mt][nt][1], acc[mt][nt][2], acc[mt][nt][3]};
#pragma unroll
            for (int q = 0; q < 4; q++) {
                const float ec = (q & 1) ? ec1 : ec0;
                const float nr = (q < 2) ? nr0 : nr8;
                if (EPI == EPI_BIAS)           v[q] = v[q] + ec;
                else if (EPI == EPI_BIAS_MISH) v[q] = mish_f(v[q] + ec);
                else if (EPI == EPI_MISH)      v[q] = mish_f(v[q]);
                else if (EPI == EPI_RBF) {
                    float d2 = nr + ec - 2.0f * v[q];
                    v[q] = expf(-sqrtf(fmaxf(d2, 0.0f)));
                }
                if (STOREMODE == ST_ROUND) v[q] = tf32_rna(v[q]);
            }
            *(float2*)(Ch + (size_t)row * N + col)       = make_float2(v[0], v[1]);
            *(float2*)(Ch + (size_t)(row + 8) * N + col) = make_float2(v[2], v[3]);
        }
    }
}

// ---------------------------------------------------------------------------
// tf32 round copy + row squared-norms
// ---------------------------------------------------------------------------
__global__ void __launch_bounds__(256)
round_tf32_k(const float4* __restrict__ in, float4* __restrict__ out, int n4)
{
    int i = blockIdx.x * 256 + threadIdx.x;
    if (i < n4) {
        float4 v = in[i];
        v.x = tf32_rna(v.x); v.y = tf32_rna(v.y);
        v.z = tf32_rna(v.z); v.w = tf32_rna(v.w);
        out[i] = v;
    }
}

__global__ void __launch_bounds__(128)
rownorm2(const float* __restrict__ X, float* __restrict__ out)
{
    const int row = blockIdx.x;
    const float4 v = *((const float4*)(X + (size_t)row * ND) + threadIdx.x);
    float s = v.x * v.x + v.y * v.y + v.z * v.z + v.w * v.w;
#pragma unroll
    for (int o = 16; o; o >>= 1) s += __shfl_down_sync(0xffffffffu, s, o);
    __shared__ float ws[4];
    const int lane = threadIdx.x & 31, w = threadIdx.x >> 5;
    if (lane == 0) ws[w] = s;
    __syncthreads();
    if (threadIdx.x == 0) out[row] = ws[0] + ws[1] + ws[2] + ws[3];
}

// ---------------------------------------------------------------------------
// Launch — big GEMM placed at 0-based launch index 4 (ncu capture slot)
// ---------------------------------------------------------------------------
extern "C" void kernel_launch(void* const* d_in, const int* in_sizes, int n_in,
                              void* d_out, int out_size)
{
    const float* x   = (const float*)d_in[0];
    const float* sm  = (const float*)d_in[1];
    const float* W1  = (const float*)d_in[2];
    const float* b1  = (const float*)d_in[3];
    const float* W2  = (const float*)d_in[4];
    const float* b2  = (const float*)d_in[5];
    const float* Wn1 = (const float*)d_in[6];
    const float* Wn2 = (const float*)d_in[7];
    float* out = (float*)d_out;

    float *tmp1, *xd, *sam, *Kb, *Hb, *nx, *ns;
    float *rx, *rsm, *rW1, *rW2, *rWn1, *rWn2;
    cudaGetSymbolAddress((void**)&tmp1, g_tmp1);
    cudaGetSymbolAddress((void**)&xd,   g_xd);
    cudaGetSymbolAddress((void**)&sam,  g_sam);
    cudaGetSymbolAddress((void**)&Kb,   g_K);
    cudaGetSymbolAddress((void**)&Hb,   g_H);
    cudaGetSymbolAddress((void**)&nx,   g_nx);
    cudaGetSymbolAddress((void**)&ns,   g_ns);
    cudaGetSymbolAddress((void**)&rx,   g_rx);
    cudaGetSymbolAddress((void**)&rsm,  g_rsm);
    cudaGetSymbolAddress((void**)&rW1,  g_rW1);
    cudaGetSymbolAddress((void**)&rW2,  g_rW2);
    cudaGetSymbolAddress((void**)&rWn1, g_rWn1);
    cudaGetSymbolAddress((void**)&rWn2, g_rWn2);

    cudaFuncSetAttribute(gemm_mma<EPI_BIAS_MISH, ST_ROUND>, cudaFuncAttributeMaxDynamicSharedMemorySize, DSMEM_BY);
    cudaFuncSetAttribute(gemm_mma<EPI_BIAS,      ST_ROUND>, cudaFuncAttributeMaxDynamicSharedMemorySize, DSMEM_BY);
    cudaFuncSetAttribute(gemm_mma<EPI_RBF,       ST_ROUND>, cudaFuncAttributeMaxDynamicSharedMemorySize, DSMEM_BY);
    cudaFuncSetAttribute(gemm_mma<EPI_MISH,      ST_ROUND>, cudaFuncAttributeMaxDynamicSharedMemorySize, DSMEM_BY);
    cudaFuncSetAttribute(gemm_mma<EPI_NONE,      ST_RAW  >, cudaFuncAttributeMaxDynamicSharedMemorySize, DSMEM_BY);

    const dim3 blk(512);

    // launches 0..3: rounding
    round_tf32_k<<<NB * ND / 4 / 256, 256>>>((const float4*)x,   (float4*)rx,   NB * ND / 4);
    round_tf32_k<<<ND * ND / 4 / 256, 256>>>((const float4*)W1,  (float4*)rW1,  ND * ND / 4);
    round_tf32_k<<<NS * NS / 4 / 256, 256>>>((const float4*)Wn1, (float4*)rWn1, NS * NS / 4);
    round_tf32_k<<<NS * NS / 4 / 256, 256>>>((const float4*)Wn2, (float4*)rWn2, NS * NS / 4);

    // launch 4: dml(x) layer 1 — ncu capture target
    gemm_mma<EPI_BIAS_MISH, ST_ROUND><<<dim3(ND / 128, NB / 256), blk, DSMEM_BY>>>(
        rx, rW1, tmp1, NB, ND, ND, b1, nullptr);

    round_tf32_k<<<ND * ND / 4 / 256, 256>>>((const float4*)W2, (float4*)rW2, ND * ND / 4);
    round_tf32_k<<<NS * ND / 4 / 256, 256>>>((const float4*)sm, (float4*)rsm, NS * ND / 4);

    gemm_mma<EPI_BIAS, ST_ROUND><<<dim3(ND / 128, NB / 256), blk, DSMEM_BY>>>(
        tmp1, rW2, xd, NB, ND, ND, b2, nullptr);
    rownorm2<<<NB, 128>>>(xd, nx);

    // dml(samples)
    gemm_mma<EPI_BIAS_MISH, ST_ROUND><<<dim3(ND / 128, NS / 256), blk, DSMEM_BY>>>(
        rsm, rW1, tmp1, NS, ND, ND, b1, nullptr);
    gemm_mma<EPI_BIAS, ST_ROUND><<<dim3(ND / 128, NS / 256), blk, DSMEM_BY>>>(
        tmp1, rW2, sam, NS, ND, ND, b2, nullptr);
    rownorm2<<<NS, 128>>>(sam, ns);

    // K = exp(-sqrt(max(nx + ns - 2*x_dml@sam^T, 0))) — single tf32 pass
    gemm_mma<EPI_RBF, ST_ROUND><<<dim3(NS / 128, NB / 256), blk, DSMEM_BY>>>(
        xd, sam, Kb, NB, NS, ND, nx, ns);

    // h = mish(K @ Wn1^T)
    gemm_mma<EPI_MISH, ST_ROUND><<<dim3(NS / 128, NB / 256), blk, DSMEM_BY>>>(
        Kb, rWn1, Hb, NB, NS, NS, nullptr, nullptr);

    // out = h @ Wn2^T
    gemm_mma<EPI_NONE, ST_RAW><<<dim3(NS / 128, NB / 256), blk, DSMEM_BY>>>(
        Hb, rWn2, out, NB, NS, NS, nullptr, nullptr);
}